// round 13
// baseline (speedup 1.0000x reference)
#include <cuda_runtime.h>
#include <cuda_fp16.h>
#include <cstdint>

// Problem constants
#define KC   1024
#define DD   64
#define BB   32
#define TT   2048
#define NV   (BB*TT)
#define QE   (BB*DD*TT)
#define DECAYF 0.99f
#define OMD    (1.0f - 0.99f)
#define COMMITF 0.25f
#define EPSF 1e-5f
#define NCAND 6
#define HBIAS 64.0f
#define NCTA 1024

// Output layout (flat float32, reference tuple order)
#define OFF_Q      0
#define OFF_LOSS   (OFF_Q + QE)
#define OFF_CODES  (OFF_LOSS + 1)
#define OFF_NEWEMB (OFF_CODES + NV)
#define OFF_NEWCS  (OFF_NEWEMB + KC*DD)
#define OFF_NEWW   (OFF_NEWCS + KC)

// Scratch (device globals — no allocation). Zero-initialized at load.
__device__ float    g_hn[KC];
__device__ uint16_t g_hnh[KC];
__device__ float    g_counts[KC];
__device__ float    g_dw[KC*DD];
__device__ float    g_loss;
__device__ __align__(256) uint16_t g_ehi[KC*DD];
// Grid-barrier state: generation counter persists across calls; cnt reset per use.
__device__ int g_gen;
__device__ int g_cnt0;
__device__ int g_cnt1;

#define SWZ(o) ((o) ^ (((o) >> 3) & 0x70))

__device__ __forceinline__ uint32_t smem_u32(const void* p) {
    uint32_t a;
    asm("{ .reg .u64 t; cvta.to.shared.u64 t, %1; cvt.u32.u64 %0, t; }" : "=r"(a) : "l"(p));
    return a;
}

#define MMA_F16A(acc, A, B0, B1)                                               \
    asm volatile("mma.sync.aligned.m16n8k16.row.col.f16.f16.f16.f16 "          \
        "{%0,%1},{%2,%3,%4,%5},{%6,%7},{%0,%1};"                               \
        : "+r"((acc)[0]), "+r"((acc)[1])                                       \
        : "r"((A)[0]), "r"((A)[1]), "r"((A)[2]), "r"((A)[3]),                  \
          "r"(B0), "r"(B1))

#define LDSM4(r0, r1, r2, r3, a)                                               \
    asm volatile("ldmatrix.sync.aligned.m8n8.x4.shared.b16 {%0,%1,%2,%3}, [%4];" \
        : "=r"(r0), "=r"(r1), "=r"(r2), "=r"(r3) : "r"(a))

#define PRMTK(d, s, i, sel)                                                    \
    asm("prmt.b32 %0, %1, %2, %3;" : "=r"(d) : "r"(s), "r"(i), "n"(sel))

#define CP_ASYNC16(dst_u32, src_ptr)                                           \
    asm volatile("cp.async.cg.shared.global [%0], [%1], 16;"                   \
                 :: "r"(dst_u32), "l"(src_ptr) : "memory")
#define CP_COMMIT() asm volatile("cp.async.commit_group;" ::: "memory")
#define CP_WAIT1()  asm volatile("cp.async.wait_group 1;" ::: "memory")
#define CP_WAIT0()  asm volatile("cp.async.wait_group 0;" ::: "memory")

// SMEM layout: A-fp16 8KB | B double buffer 2x8KB | hn-half2 2KB
#define SM_AH    0
#define SM_B     8192
#define SM_HN    24576
#define SM_CAND  SM_AH
#define SM_TOTAL (SM_HN + 2048 + 128)   // 26752

extern __shared__ __align__(1024) char smc[];

// Insert 2 keys into sorted ascending top-2 (v0<=v1). 6 IMNMX.
__device__ __forceinline__ void ins2p(uint32_t v[2], uint32_t a, uint32_t b) {
    uint32_t a0 = min(a, b), a1 = max(a, b);
    uint32_t x = min(v[0], a0);
    uint32_t y = max(v[0], a0);
    uint32_t z = min(v[1], a1);
    v[0] = x;
    v[1] = min(y, z);
}
__device__ __forceinline__ void ins6u(uint32_t v[6], uint32_t t) {
    #pragma unroll
    for (int i = 0; i < 6; ++i) {
        uint32_t lo = min(t, v[i]);
        t = max(t, v[i]);
        v[i] = lo;
    }
}

__device__ __forceinline__ void load_bchunk_async(uint32_t sb, int c, int buf, int tid) {
    #pragma unroll
    for (int i = 0; i < 4; ++i) {
        int idx  = tid + i * 128;
        int code = idx >> 3;
        int ch   = idx & 7;
        const uint16_t* src = g_ehi + (size_t)(c * 64 + code) * DD + ch * 8;
        uint32_t doff = SM_B + buf * 8192 + code * 128 + ((ch ^ (code & 7)) * 16);
        CP_ASYNC16(sb + doff, src);
    }
}

// Sense-reversing grid barrier (all NCTA CTAs co-resident).
__device__ __forceinline__ void grid_barrier(int* cnt, int target, int tid) {
    __syncthreads();
    __threadfence();
    if (tid == 0) {
        if (atomicAdd(cnt, 1) == NCTA - 1) {
            *cnt = 0;                       // safe: all arrived, nobody reads until next call
            __threadfence();
            atomicAdd(&g_gen, 1);
        } else {
            while (*(volatile int*)&g_gen - target < 0) __nanosleep(64);
        }
    }
    __syncthreads();
    __threadfence();
}

__global__ __launch_bounds__(128, 8) void vq_fused(
        const float* __restrict__ z,
        const float* __restrict__ emb,
        const float* __restrict__ ema_cs,
        const float* __restrict__ ema_w,
        float* __restrict__ out) {
    __shared__ float swr[4];
    __shared__ int   sgen;
    const int tid  = threadIdx.x;
    const int wid  = tid >> 5;
    const int lane = tid & 31;
    const uint32_t sb = smem_u32(smc);
    const int cta = blockIdx.x;

    if (tid == 0) sgen = *(volatile int*)&g_gen;

    const int n0 = cta * 64;
    const int b  = n0 >> 11;
    const int t0 = n0 & 2047;
    const float* zb = z + (size_t)b * (DD * TT) + t0;

    // ---- Prep share: CTA k owns code k — zero dw/count, fp16 convert, half-norm
    {
        float sq = 0.0f;
        if (tid < 64) {
            g_dw[(size_t)cta * 64 + tid] = 0.0f;
            float f = emb[(size_t)cta * 64 + tid];
            __half h = __float2half_rn(f);
            g_ehi[(size_t)cta * 64 + tid] = reinterpret_cast<uint16_t&>(h);
            sq = f * f;
        }
        #pragma unroll
        for (int o = 16; o; o >>= 1) sq += __shfl_xor_sync(0xffffffffu, sq, o);
        if (lane == 0) swr[wid] = sq;
        __syncthreads();
        if (tid == 0) {
            float hn = 0.5f * (swr[0] + swr[1] + swr[2] + swr[3]);
            g_hn[cta] = hn;
            __half hh = __float2half_rn(hn + HBIAS);
            g_hnh[cta] = reinterpret_cast<uint16_t&>(hh);
            g_counts[cta] = 0.0f;
            if (cta == 0) g_loss = 0.0f;
        }
        __syncthreads();
    }

    // ---- Stage A (local, overlapped with other CTAs' prep): z -> -fp16 swizzled
    {
        int r  = tid & 63;
        int hf = tid >> 6;
        const float* zr = zb + r;
        #pragma unroll
        for (int j = 0; j < 16; ++j) {
            int d = hf * 32 + 2 * j;
            __half h0 = __float2half_rn(-zr[(size_t)d * TT]);
            __half h1 = __float2half_rn(-zr[(size_t)(d + 1) * TT]);
            uint32_t hp = (uint32_t)reinterpret_cast<uint16_t&>(h0)
                        | ((uint32_t)reinterpret_cast<uint16_t&>(h1) << 16);
            *(uint32_t*)(smc + SM_AH + SWZ((uint32_t)(r * 128 + 2 * d))) = hp;
        }
    }

    const int gen0 = sgen;            // sgen valid: set before first __syncthreads above
    // ---- Barrier 0: all prep shares visible before any B prefetch / hn load
    grid_barrier(&g_cnt0, gen0 + 1, tid);

    // biased hn table as half2 words
    uint32_t* shn2 = (uint32_t*)(smc + SM_HN);
    #pragma unroll
    for (int i = 0; i < 4; ++i)
        shn2[tid + i * 128] = ((const uint32_t*)g_hnh)[tid + i * 128];

    load_bchunk_async(sb, 0, 0, tid); CP_COMMIT();
    load_bchunk_async(sb, 1, 1, tid); CP_COMMIT();

    __syncthreads();

    // ldmatrix lane constants
    const uint32_t r7 = (uint32_t)(lane & 7);
    const uint32_t mm = (uint32_t)(lane >> 3);

    uint32_t ah[4][4];
    {
        uint32_t arow = (uint32_t)(wid * 16) + (mm & 1) * 8 + r7;
        uint32_t acol = (mm >> 1) * 16;
        #pragma unroll
        for (int s = 0; s < 4; ++s) {
            uint32_t addr = sb + SM_AH + arow * 128
                          + (((uint32_t)(s * 32) + acol) ^ (r7 * 16));
            LDSM4(ah[s][0], ah[s][1], ah[s][2], ah[s][3], addr);
        }
    }

    const uint32_t blconst = r7 * 128 + ((mm * 16) ^ (r7 * 16));
    const uint32_t q2 = (uint32_t)((lane & 3) * 2);
    uint32_t ie = q2 | ((q2 + 1) << 16);
    uint32_t tv[2][2] = {{0xFFFFFFFFu, 0xFFFFFFFFu}, {0xFFFFFFFFu, 0xFFFFFFFFu}};

    // ---- Chunk loop: 16 chunks x 64 codes (identical to r12)
    #pragma unroll 1
    for (int c = 0; c < 16; ++c) {
        if (c < 15) CP_WAIT1(); else CP_WAIT0();
        __syncthreads();
        const uint32_t bbase = sb + SM_B + (uint32_t)((c & 1) * 8192) + blconst;

        #pragma unroll 1
        for (int nt = 0; nt < 8; ++nt) {
            uint32_t a1 = bbase + (uint32_t)(nt * 1024);
            uint32_t a2 = a1 ^ 64u;
            uint32_t bh[4][2];
            LDSM4(bh[0][0], bh[0][1], bh[1][0], bh[1][1], a1);
            LDSM4(bh[2][0], bh[2][1], bh[3][0], bh[3][1], a2);

            uint32_t h01 = shn2[c * 32 + nt * 4 + (lane & 3)];
            uint32_t aA[2] = {h01, h01};
            MMA_F16A(aA, ah[0], bh[0][0], bh[0][1]);
            MMA_F16A(aA, ah[1], bh[1][0], bh[1][1]);
            MMA_F16A(aA, ah[2], bh[2][0], bh[2][1]);
            MMA_F16A(aA, ah[3], bh[3][0], bh[3][1]);

            uint32_t k0e, k0o, k1e, k1o;
            PRMTK(k0e, aA[0], ie, 0x1054);
            PRMTK(k0o, aA[0], ie, 0x3276);
            PRMTK(k1e, aA[1], ie, 0x1054);
            PRMTK(k1o, aA[1], ie, 0x3276);
            ins2p(tv[0], k0e, k0o);
            ins2p(tv[1], k1e, k1o);
            ie += 0x00080008u;
        }
        __syncthreads();
        if (c < 14) { load_bchunk_async(sb, c + 2, c & 1, tid); CP_COMMIT(); }
    }

    // ---- Cross-lane merge -> top-6 candidates per row
    int* ci = (int*)(smc + SM_CAND);
    #pragma unroll
    for (int s = 0; s < 2; ++s) {
        uint32_t m[6] = {tv[s][0], tv[s][1],
                         0xFFFFFFFFu, 0xFFFFFFFFu, 0xFFFFFFFFu, 0xFFFFFFFFu};
        #pragma unroll
        for (int off = 1; off <= 2; off <<= 1) {
            uint32_t p[6];
            #pragma unroll
            for (int j = 0; j < 6; ++j) p[j] = __shfl_xor_sync(0xffffffffu, m[j], off);
            #pragma unroll
            for (int j = 0; j < 6; ++j) ins6u(m, p[j]);
        }
        if ((lane & 3) == 0) {
            int row = wid * 16 + s * 8 + (lane >> 2);
            #pragma unroll
            for (int j = 0; j < NCAND; ++j)
                ci[row * NCAND + j] = (int)(m[j] & 0xFFFFu);
        }
    }
    __syncthreads();

    // ---- Epilogue: 2 threads per row, each owns 32 dims
    const int row = tid >> 1;
    const int hh  = tid & 1;
    const float* zr = zb + row;

    float zh[32];
    #pragma unroll
    for (int k = 0; k < 32; ++k) zh[k] = zr[(size_t)(hh * 32 + k) * TT];

    float bestv = 3.4e38f;
    int   besti = 0;
    #pragma unroll
    for (int j = 0; j < NCAND; ++j) {
        int idx = ci[row * NCAND + j];
        const float4* er = (const float4*)(emb + (size_t)idx * DD + hh * 32);
        float dot = 0.0f;
        #pragma unroll
        for (int q = 0; q < 8; ++q) {
            float4 e4 = __ldg(er + q);
            dot = fmaf(zh[4 * q + 0], e4.x, dot);
            dot = fmaf(zh[4 * q + 1], e4.y, dot);
            dot = fmaf(zh[4 * q + 2], e4.z, dot);
            dot = fmaf(zh[4 * q + 3], e4.w, dot);
        }
        dot += __shfl_xor_sync(0xffffffffu, dot, 1);
        float v = g_hn[idx] - dot;
        if (v < bestv || (v == bestv && idx < besti)) { bestv = v; besti = idx; }
    }

    const float4* er = (const float4*)(emb + (size_t)besti * DD + hh * 32);
    float* oq = out + OFF_Q + (size_t)b * (DD * TT) + t0 + row;
    float* dwp = g_dw + (size_t)besti * DD + hh * 32;
    float lsum = 0.0f;
    #pragma unroll
    for (int q = 0; q < 8; ++q) {
        float4 e4 = __ldg(er + q);
        int d = hh * 32 + 4 * q;
        oq[(size_t)(d + 0) * TT] = e4.x;
        oq[(size_t)(d + 1) * TT] = e4.y;
        oq[(size_t)(d + 2) * TT] = e4.z;
        oq[(size_t)(d + 3) * TT] = e4.w;
        float q0 = e4.x - zh[4 * q + 0], q1 = e4.y - zh[4 * q + 1];
        float q2v = e4.z - zh[4 * q + 2], q3 = e4.w - zh[4 * q + 3];
        lsum += q0 * q0 + q1 * q1 + q2v * q2v + q3 * q3;
        asm volatile("red.global.add.v4.f32 [%0], {%1,%2,%3,%4};"
                     :: "l"(dwp + 4 * q),
                        "f"(zh[4 * q + 0]), "f"(zh[4 * q + 1]),
                        "f"(zh[4 * q + 2]), "f"(zh[4 * q + 3]) : "memory");
    }
    if (hh == 0) {
        out[OFF_CODES + n0 + row] = (float)besti;
        atomicAdd(&g_counts[besti], 1.0f);
    }

    #pragma unroll
    for (int o = 16; o; o >>= 1) lsum += __shfl_xor_sync(0xffffffffu, lsum, o);
    if (lane == 0) swr[wid] = lsum;
    __syncthreads();
    if (tid == 0)
        atomicAdd(&g_loss, swr[0] + swr[1] + swr[2] + swr[3]);

    // ---- Barrier 1: all counts/dw/loss complete
    grid_barrier(&g_cnt1, gen0 + 2, tid);

    // ---- Fin share: CTA k owns code k (64 output elems)
    {
        float s = 0.0f;
        #pragma unroll
        for (int j = 0; j < 8; ++j) {
            int k = tid * 8 + j;
            s += DECAYF * ema_cs[k] + OMD * g_counts[k];
        }
        #pragma unroll
        for (int o = 16; o; o >>= 1) s += __shfl_xor_sync(0xffffffffu, s, o);
        if (lane == 0) swr[wid] = s;
        __syncthreads();
        float nsum = swr[0] + swr[1] + swr[2] + swr[3];

        float cs = DECAYF * ema_cs[cta] + OMD * g_counts[cta];
        if (tid == 0) {
            out[OFF_NEWCS + cta] = cs;
            if (cta == 0) out[OFF_LOSS] = COMMITF * g_loss * (1.0f / (float)QE);
        }
        float cluster = (cs + EPSF) / (nsum + (float)KC * EPSF) * nsum;
        if (tid < 64) {
            int i = cta * 64 + tid;
            float nw = DECAYF * ema_w[i] + OMD * g_dw[i];
            out[OFF_NEWW + i] = nw;
            out[OFF_NEWEMB + i] = nw * (1.0f / cluster);
        }
    }
}

// ---------------------------------------------------------------------------
extern "C" void kernel_launch(void* const* d_in, const int* in_sizes, int n_in,
                              void* d_out, int out_size) {
    const float* z      = (const float*)d_in[0];
    const float* emb    = (const float*)d_in[1];
    const float* ema_cs = (const float*)d_in[2];
    const float* ema_w  = (const float*)d_in[3];
    float* out = (float*)d_out;

    vq_fused<<<NCTA, 128, SM_TOTAL>>>(z, emb, ema_cs, ema_w, out);
}

// round 14
// speedup vs baseline: 1.0170x; 1.0170x over previous
#include <cuda_runtime.h>
#include <cuda_fp16.h>
#include <cstdint>

// Problem constants
#define KC   1024
#define DD   64
#define BB   32
#define TT   2048
#define NV   (BB*TT)
#define QE   (BB*DD*TT)
#define DECAYF 0.99f
#define OMD    (1.0f - 0.99f)
#define COMMITF 0.25f
#define EPSF 1e-5f
#define NCAND 6
#define HBIAS 64.0f

// Output layout (flat float32, reference tuple order)
#define OFF_Q      0
#define OFF_LOSS   (OFF_Q + QE)
#define OFF_CODES  (OFF_LOSS + 1)
#define OFF_NEWEMB (OFF_CODES + NV)
#define OFF_NEWCS  (OFF_NEWEMB + KC*DD)
#define OFF_NEWW   (OFF_NEWCS + KC)

// Scratch (device globals — no allocation)
__device__ float    g_hn[KC];
__device__ uint16_t g_hnh[KC];
__device__ float    g_counts[KC];
__device__ float    g_dw[KC*DD];
__device__ float    g_loss;
__device__ __align__(256) uint16_t g_ehi[KC*DD];

#define SWZ(o) ((o) ^ (((o) >> 3) & 0x70))

__device__ __forceinline__ uint32_t smem_u32(const void* p) {
    uint32_t a;
    asm("{ .reg .u64 t; cvta.to.shared.u64 t, %1; cvt.u32.u64 %0, t; }" : "=r"(a) : "l"(p));
    return a;
}

#define MMA_F16A(acc, A, B0, B1)                                               \
    asm volatile("mma.sync.aligned.m16n8k16.row.col.f16.f16.f16.f16 "          \
        "{%0,%1},{%2,%3,%4,%5},{%6,%7},{%0,%1};"                               \
        : "+r"((acc)[0]), "+r"((acc)[1])                                       \
        : "r"((A)[0]), "r"((A)[1]), "r"((A)[2]), "r"((A)[3]),                  \
          "r"(B0), "r"(B1))

#define LDSM4(r0, r1, r2, r3, a)                                               \
    asm volatile("ldmatrix.sync.aligned.m8n8.x4.shared.b16 {%0,%1,%2,%3}, [%4];" \
        : "=r"(r0), "=r"(r1), "=r"(r2), "=r"(r3) : "r"(a))

#define PRMTK(d, s, i, sel)                                                    \
    asm("prmt.b32 %0, %1, %2, %3;" : "=r"(d) : "r"(s), "r"(i), "n"(sel))

#define CP_ASYNC16(dst_u32, src_ptr)                                           \
    asm volatile("cp.async.cg.shared.global [%0], [%1], 16;"                   \
                 :: "r"(dst_u32), "l"(src_ptr) : "memory")
#define CP_COMMIT() asm volatile("cp.async.commit_group;" ::: "memory")
#define CP_WAIT1()  asm volatile("cp.async.wait_group 1;" ::: "memory")
#define CP_WAIT0()  asm volatile("cp.async.wait_group 0;" ::: "memory")

// SMEM layout: A-fp16 16KB (128 rows) | B double buffer 2x8KB | hn-half2 2KB
#define SM_AH    0
#define SM_B     16384
#define SM_HN    32768
#define SM_CAND  SM_AH                  // reused after MMA loop (128*6 ints)
#define SM_TOTAL (SM_HN + 2048 + 128)   // 34944

// ---------------------------------------------------------------------------
// Prep: zero scratch, fp16 embedding, warp-per-code half-norms (+bias)
// ---------------------------------------------------------------------------
__global__ void vq_prep(const float* __restrict__ emb) {
    int i = blockIdx.x * 256 + threadIdx.x;   // 65536 threads
    g_dw[i] = 0.0f;
    {
        __half h = __float2half_rn(emb[i]);
        g_ehi[i] = reinterpret_cast<uint16_t&>(h);
    }
    int w = i >> 5;
    int lane = i & 31;
    if (w < KC) {
        const float2* r = (const float2*)(emb + (size_t)w * DD);
        float2 v = r[lane];
        float s = v.x * v.x + v.y * v.y;
        #pragma unroll
        for (int o = 16; o; o >>= 1) s += __shfl_xor_sync(0xffffffffu, s, o);
        if (lane == 0) {
            float hn = 0.5f * s;
            g_hn[w] = hn;
            __half hh = __float2half_rn(hn + HBIAS);
            g_hnh[w] = reinterpret_cast<uint16_t&>(hh);
            g_counts[w] = 0.0f;
        }
    }
    if (i == 0) g_loss = 0.0f;
}

// ---------------------------------------------------------------------------
// Main: M=128/CTA (2 m-tiles/warp), B fragments amortized over 2 MMAs
// ---------------------------------------------------------------------------
extern __shared__ __align__(1024) char smc[];

// Insert 2 keys into sorted ascending top-2 (v0<=v1). 6 IMNMX.
__device__ __forceinline__ void ins2p(uint32_t v[2], uint32_t a, uint32_t b) {
    uint32_t a0 = min(a, b), a1 = max(a, b);
    uint32_t x = min(v[0], a0);
    uint32_t y = max(v[0], a0);
    uint32_t z = min(v[1], a1);
    v[0] = x;
    v[1] = min(y, z);
}
__device__ __forceinline__ void ins6u(uint32_t v[6], uint32_t t) {
    #pragma unroll
    for (int i = 0; i < 6; ++i) {
        uint32_t lo = min(t, v[i]);
        t = max(t, v[i]);
        v[i] = lo;
    }
}

// Load one 64-code B chunk (8KB) into buf
__device__ __forceinline__ void load_bchunk_async(uint32_t sb, int c, int buf, int tid) {
    #pragma unroll
    for (int i = 0; i < 4; ++i) {
        int idx  = tid + i * 128;
        int code = idx >> 3;
        int ch   = idx & 7;
        const uint16_t* src = g_ehi + (size_t)(c * 64 + code) * DD + ch * 8;
        uint32_t doff = SM_B + buf * 8192 + code * 128 + ((ch ^ (code & 7)) * 16);
        CP_ASYNC16(sb + doff, src);
    }
}

__global__ __launch_bounds__(128, 6) void vq_main_mma(
        const float* __restrict__ z,
        const float* __restrict__ emb,
        float* __restrict__ out) {
    __shared__ float swr[4];
    const int tid  = threadIdx.x;
    const int wid  = tid >> 5;
    const int lane = tid & 31;
    const uint32_t sb = smem_u32(smc);

    const int n0 = blockIdx.x * 128;         // first vector of this CTA
    const int b  = n0 >> 11;
    const int t0 = n0 & 2047;
    const float* zb = z + (size_t)b * (DD * TT) + t0;

    // --- Stage A: 1 thread per row, 64 dims; NEGATED fp16, swizzled
    {
        const float* zr = zb + tid;
        #pragma unroll
        for (int j = 0; j < 32; ++j) {
            int d = 2 * j;
            __half h0 = __float2half_rn(-zr[(size_t)d * TT]);
            __half h1 = __float2half_rn(-zr[(size_t)(d + 1) * TT]);
            uint32_t hp = (uint32_t)reinterpret_cast<uint16_t&>(h0)
                        | ((uint32_t)reinterpret_cast<uint16_t&>(h1) << 16);
            *(uint32_t*)(smc + SM_AH + SWZ((uint32_t)(tid * 128 + 2 * d))) = hp;
        }
    }
    // biased hn table as half2 words
    uint32_t* shn2 = (uint32_t*)(smc + SM_HN);
    #pragma unroll
    for (int i = 0; i < 4; ++i)
        shn2[tid + i * 128] = ((const uint32_t*)g_hnh)[tid + i * 128];

    // Prefetch B chunks 0, 1
    load_bchunk_async(sb, 0, 0, tid); CP_COMMIT();
    load_bchunk_async(sb, 1, 1, tid); CP_COMMIT();

    __syncthreads();

    // ldmatrix lane constants
    const uint32_t r7 = (uint32_t)(lane & 7);
    const uint32_t mm = (uint32_t)(lane >> 3);

    // --- A fragments: 2 m-tiles/warp (rows wid*32 .. +31), 4 k-steps x 4 regs
    uint32_t ah[2][4][4];
    #pragma unroll
    for (int mt = 0; mt < 2; ++mt) {
        uint32_t arow = (uint32_t)(wid * 32 + mt * 16) + (mm & 1) * 8 + r7;
        uint32_t acol = (mm >> 1) * 16;
        #pragma unroll
        for (int s = 0; s < 4; ++s) {
            uint32_t addr = sb + SM_AH + arow * 128
                          + (((uint32_t)(s * 32) + acol) ^ (r7 * 16));
            LDSM4(ah[mt][s][0], ah[mt][s][1], ah[mt][s][2], ah[mt][s][3], addr);
        }
    }

    const uint32_t blconst = r7 * 128 + ((mm * 16) ^ (r7 * 16));
    const uint32_t q2 = (uint32_t)((lane & 3) * 2);
    uint32_t ie = q2 | ((q2 + 1) << 16);

    // 4 row-slot trackers: [mt0 row, mt0 row+8, mt1 row, mt1 row+8]
    uint32_t tv[4][2];
    #pragma unroll
    for (int s = 0; s < 4; ++s) { tv[s][0] = 0xFFFFFFFFu; tv[s][1] = 0xFFFFFFFFu; }

    // --- Chunk loop: 16 chunks x 64 codes; B loaded once, used by 2 m-tiles
    #pragma unroll 1
    for (int c = 0; c < 16; ++c) {
        if (c < 15) CP_WAIT1(); else CP_WAIT0();
        __syncthreads();
        const uint32_t bbase = sb + SM_B + (uint32_t)((c & 1) * 8192) + blconst;

        #pragma unroll 1
        for (int nt = 0; nt < 8; ++nt) {
            uint32_t a1 = bbase + (uint32_t)(nt * 1024);
            uint32_t a2 = a1 ^ 64u;
            uint32_t bh[4][2];
            LDSM4(bh[0][0], bh[0][1], bh[1][0], bh[1][1], a1);  // k-halves 0-3
            LDSM4(bh[2][0], bh[2][1], bh[3][0], bh[3][1], a2);  // k-halves 4-7

            uint32_t h01 = shn2[c * 32 + nt * 4 + (lane & 3)];
            uint32_t aA0[2] = {h01, h01};
            uint32_t aA1[2] = {h01, h01};
            MMA_F16A(aA0, ah[0][0], bh[0][0], bh[0][1]);
            MMA_F16A(aA1, ah[1][0], bh[0][0], bh[0][1]);
            MMA_F16A(aA0, ah[0][1], bh[1][0], bh[1][1]);
            MMA_F16A(aA1, ah[1][1], bh[1][0], bh[1][1]);
            MMA_F16A(aA0, ah[0][2], bh[2][0], bh[2][1]);
            MMA_F16A(aA1, ah[1][2], bh[2][0], bh[2][1]);
            MMA_F16A(aA0, ah[0][3], bh[3][0], bh[3][1]);
            MMA_F16A(aA1, ah[1][3], bh[3][0], bh[3][1]);

            uint32_t k0, k1;
            PRMTK(k0, aA0[0], ie, 0x1054);
            PRMTK(k1, aA0[0], ie, 0x3276);
            ins2p(tv[0], k0, k1);
            PRMTK(k0, aA0[1], ie, 0x1054);
            PRMTK(k1, aA0[1], ie, 0x3276);
            ins2p(tv[1], k0, k1);
            PRMTK(k0, aA1[0], ie, 0x1054);
            PRMTK(k1, aA1[0], ie, 0x3276);
            ins2p(tv[2], k0, k1);
            PRMTK(k0, aA1[1], ie, 0x1054);
            PRMTK(k1, aA1[1], ie, 0x3276);
            ins2p(tv[3], k0, k1);
            ie += 0x00080008u;
        }
        __syncthreads();
        if (c < 14) { load_bchunk_async(sb, c + 2, c & 1, tid); CP_COMMIT(); }
    }

    // --- Cross-lane butterfly merge (4 lanes, disjoint code sets) -> top-6
    int* ci = (int*)(smc + SM_CAND);
    #pragma unroll
    for (int s = 0; s < 4; ++s) {
        uint32_t m[6] = {tv[s][0], tv[s][1],
                         0xFFFFFFFFu, 0xFFFFFFFFu, 0xFFFFFFFFu, 0xFFFFFFFFu};
        #pragma unroll
        for (int off = 1; off <= 2; off <<= 1) {
            uint32_t p[6];
            #pragma unroll
            for (int j = 0; j < 6; ++j) p[j] = __shfl_xor_sync(0xffffffffu, m[j], off);
            #pragma unroll
            for (int j = 0; j < 6; ++j) ins6u(m, p[j]);
        }
        if ((lane & 3) == 0) {
            int row = wid * 32 + (s >> 1) * 16 + (s & 1) * 8 + (lane >> 2);
            #pragma unroll
            for (int j = 0; j < NCAND; ++j)
                ci[row * NCAND + j] = (int)(m[j] & 0xFFFFu);
        }
    }
    __syncthreads();

    // --- Epilogue: two 64-row groups, 2 threads per row, each owns 32 dims
    float lsum = 0.0f;
    #pragma unroll 1
    for (int g = 0; g < 2; ++g) {
        const int row = g * 64 + (tid >> 1);
        const int hh  = tid & 1;
        const float* zr = zb + row;

        float zh[32];
        #pragma unroll
        for (int k = 0; k < 32; ++k) zh[k] = zr[(size_t)(hh * 32 + k) * TT];

        float bestv = 3.4e38f;
        int   besti = 0;
        #pragma unroll
        for (int j = 0; j < NCAND; ++j) {
            int idx = ci[row * NCAND + j];
            const float4* er = (const float4*)(emb + (size_t)idx * DD + hh * 32);
            float dot = 0.0f;
            #pragma unroll
            for (int q = 0; q < 8; ++q) {
                float4 e4 = __ldg(er + q);
                dot = fmaf(zh[4 * q + 0], e4.x, dot);
                dot = fmaf(zh[4 * q + 1], e4.y, dot);
                dot = fmaf(zh[4 * q + 2], e4.z, dot);
                dot = fmaf(zh[4 * q + 3], e4.w, dot);
            }
            dot += __shfl_xor_sync(0xffffffffu, dot, 1);
            float v = g_hn[idx] - dot;
            if (v < bestv || (v == bestv && idx < besti)) { bestv = v; besti = idx; }
        }

        const float4* er = (const float4*)(emb + (size_t)besti * DD + hh * 32);
        float* oq = out + OFF_Q + (size_t)b * (DD * TT) + t0 + row;
        float* dwp = g_dw + (size_t)besti * DD + hh * 32;
        #pragma unroll
        for (int q = 0; q < 8; ++q) {
            float4 e4 = __ldg(er + q);
            int d = hh * 32 + 4 * q;
            oq[(size_t)(d + 0) * TT] = e4.x;
            oq[(size_t)(d + 1) * TT] = e4.y;
            oq[(size_t)(d + 2) * TT] = e4.z;
            oq[(size_t)(d + 3) * TT] = e4.w;
            float q0 = e4.x - zh[4 * q + 0], q1 = e4.y - zh[4 * q + 1];
            float q2v = e4.z - zh[4 * q + 2], q3 = e4.w - zh[4 * q + 3];
            lsum += q0 * q0 + q1 * q1 + q2v * q2v + q3 * q3;
            asm volatile("red.global.add.v4.f32 [%0], {%1,%2,%3,%4};"
                         :: "l"(dwp + 4 * q),
                            "f"(zh[4 * q + 0]), "f"(zh[4 * q + 1]),
                            "f"(zh[4 * q + 2]), "f"(zh[4 * q + 3]) : "memory");
        }
        if (hh == 0) {
            out[OFF_CODES + n0 + row] = (float)besti;
            atomicAdd(&g_counts[besti], 1.0f);
        }
    }

    #pragma unroll
    for (int o = 16; o; o >>= 1) lsum += __shfl_xor_sync(0xffffffffu, lsum, o);
    if (lane == 0) swr[wid] = lsum;
    __syncthreads();
    if (tid == 0)
        atomicAdd(&g_loss, swr[0] + swr[1] + swr[2] + swr[3]);
}

// ---------------------------------------------------------------------------
// Finalize (merged): per-block nsum reduction, new_cs/loss (block 0),
// new_w + new_embedding everywhere.  256 blocks x 256 threads.
// ---------------------------------------------------------------------------
__global__ __launch_bounds__(256) void vq_fin(
        const float* __restrict__ ema_cs,
        const float* __restrict__ ema_w,
        float* __restrict__ out) {
    __shared__ float sw[8];
    __shared__ float snv;
    int tid = threadIdx.x;
    int i = blockIdx.x * 256 + tid;

    float s = 0.0f;
    #pragma unroll
    for (int j = 0; j < 4; ++j) {
        int k = tid * 4 + j;
        s += DECAYF * ema_cs[k] + OMD * g_counts[k];
    }
    #pragma unroll
    for (int o = 16; o; o >>= 1) s += __shfl_xor_sync(0xffffffffu, s, o);
    if ((tid & 31) == 0) sw[tid >> 5] = s;
    __syncthreads();
    if (tid < 32) {
        float u = (tid < 8) ? sw[tid] : 0.0f;
        #pragma unroll
        for (int o = 4; o; o >>= 1) u += __shfl_xor_sync(0xffffffffu, u, o);
        if (tid == 0) snv = u;
    }
    __syncthreads();
    float nsum = snv;

    if (blockIdx.x == 0) {
        #pragma unroll
        for (int j = 0; j < 4; ++j) {
            int k = tid * 4 + j;
            out[OFF_NEWCS + k] = DECAYF * ema_cs[k] + OMD * g_counts[k];
        }
        if (tid == 0) out[OFF_LOSS] = COMMITF * g_loss * (1.0f / (float)QE);
    }

    int k = i >> 6;
    float cs = DECAYF * ema_cs[k] + OMD * g_counts[k];
    float cluster = (cs + EPSF) / (nsum + (float)KC * EPSF) * nsum;
    float nw = DECAYF * ema_w[i] + OMD * g_dw[i];
    out[OFF_NEWW + i] = nw;
    out[OFF_NEWEMB + i] = nw * (1.0f / cluster);
}

// ---------------------------------------------------------------------------
extern "C" void kernel_launch(void* const* d_in, const int* in_sizes, int n_in,
                              void* d_out, int out_size) {
    const float* z      = (const float*)d_in[0];
    const float* emb    = (const float*)d_in[1];
    const float* ema_cs = (const float*)d_in[2];
    const float* ema_w  = (const float*)d_in[3];
    float* out = (float*)d_out;

    cudaFuncSetAttribute(vq_main_mma, cudaFuncAttributeMaxDynamicSharedMemorySize, SM_TOTAL);

    vq_prep<<<256, 256>>>(emb);
    vq_main_mma<<<512, 128, SM_TOTAL>>>(z, emb, out);
    vq_fin<<<256, 256>>>(ema_cs, ema_w, out);
}

// round 15
// speedup vs baseline: 1.1444x; 1.1253x over previous
#include <cuda_runtime.h>
#include <cuda_fp16.h>
#include <cstdint>

// Problem constants
#define KC   1024
#define DD   64
#define BB   32
#define TT   2048
#define NV   (BB*TT)
#define QE   (BB*DD*TT)
#define DECAYF 0.99f
#define OMD    (1.0f - 0.99f)
#define COMMITF 0.25f
#define EPSF 1e-5f
#define NCAND 6
#define HBIAS 64.0f

// Output layout (flat float32, reference tuple order)
#define OFF_Q      0
#define OFF_LOSS   (OFF_Q + QE)
#define OFF_CODES  (OFF_LOSS + 1)
#define OFF_NEWEMB (OFF_CODES + NV)
#define OFF_NEWCS  (OFF_NEWEMB + KC*DD)
#define OFF_NEWW   (OFF_NEWCS + KC)

// Scratch (device globals — no allocation)
__device__ float    g_hn[KC];
__device__ uint16_t g_hnh[KC];
__device__ float    g_counts[KC];
__device__ float    g_dw[KC*DD];
__device__ float    g_loss;
__device__ __align__(256) uint16_t g_ehi[KC*DD];

#define SWZ(o) ((o) ^ (((o) >> 3) & 0x70))

__device__ __forceinline__ uint32_t smem_u32(const void* p) {
    uint32_t a;
    asm("{ .reg .u64 t; cvta.to.shared.u64 t, %1; cvt.u32.u64 %0, t; }" : "=r"(a) : "l"(p));
    return a;
}

#define MMA_F16A(acc, A, B0, B1)                                               \
    asm volatile("mma.sync.aligned.m16n8k16.row.col.f16.f16.f16.f16 "          \
        "{%0,%1},{%2,%3,%4,%5},{%6,%7},{%0,%1};"                               \
        : "+r"((acc)[0]), "+r"((acc)[1])                                       \
        : "r"((A)[0]), "r"((A)[1]), "r"((A)[2]), "r"((A)[3]),                  \
          "r"(B0), "r"(B1))

#define LDSM4(r0, r1, r2, r3, a)                                               \
    asm volatile("ldmatrix.sync.aligned.m8n8.x4.shared.b16 {%0,%1,%2,%3}, [%4];" \
        : "=r"(r0), "=r"(r1), "=r"(r2), "=r"(r3) : "r"(a))

#define PRMTK(d, s, i, sel)                                                    \
    asm("prmt.b32 %0, %1, %2, %3;" : "=r"(d) : "r"(s), "r"(i), "n"(sel))

#define CP_ASYNC16(dst_u32, src_ptr)                                           \
    asm volatile("cp.async.cg.shared.global [%0], [%1], 16;"                   \
                 :: "r"(dst_u32), "l"(src_ptr) : "memory")
#define CP_COMMIT() asm volatile("cp.async.commit_group;" ::: "memory")
#define CP_WAIT1()  asm volatile("cp.async.wait_group 1;" ::: "memory")
#define CP_WAIT0()  asm volatile("cp.async.wait_group 0;" ::: "memory")

// SMEM layout: A-fp16 8KB | B 4 buffers x 4KB | hn-half2 2KB
// B buffer index = half*2 + (c&1)
#define SM_AH    0
#define SM_B     8192
#define SM_HN    24576
#define SM_KEY   SM_AH                  // reused after MMA loop (128*6 keys)
#define SM_TOTAL (SM_HN + 2048 + 128)   // 26752

// ---------------------------------------------------------------------------
// Prep: zero scratch, fp16 embedding, warp-per-code half-norms (+bias)
// ---------------------------------------------------------------------------
__global__ void vq_prep(const float* __restrict__ emb) {
    int i = blockIdx.x * 256 + threadIdx.x;   // 65536 threads
    g_dw[i] = 0.0f;
    {
        __half h = __float2half_rn(emb[i]);
        g_ehi[i] = reinterpret_cast<uint16_t&>(h);
    }
    int w = i >> 5;
    int lane = i & 31;
    if (w < KC) {
        const float2* r = (const float2*)(emb + (size_t)w * DD);
        float2 v = r[lane];
        float s = v.x * v.x + v.y * v.y;
        #pragma unroll
        for (int o = 16; o; o >>= 1) s += __shfl_xor_sync(0xffffffffu, s, o);
        if (lane == 0) {
            float hn = 0.5f * s;
            g_hn[w] = hn;
            __half hh = __float2half_rn(hn + HBIAS);
            g_hnh[w] = reinterpret_cast<uint16_t&>(hh);
            g_counts[w] = 0.0f;
        }
    }
    if (i == 0) g_loss = 0.0f;
}

// ---------------------------------------------------------------------------
// Main: M=64/CTA, warp-pairs split codes; each warp = 2 m-tiles x 512 codes
// ---------------------------------------------------------------------------
extern __shared__ __align__(1024) char smc[];

__device__ __forceinline__ void ins2p(uint32_t v[2], uint32_t a, uint32_t b) {
    uint32_t a0 = min(a, b), a1 = max(a, b);
    uint32_t x = min(v[0], a0);
    uint32_t y = max(v[0], a0);
    uint32_t z = min(v[1], a1);
    v[0] = x;
    v[1] = min(y, z);
}
__device__ __forceinline__ void ins6u(uint32_t v[6], uint32_t t) {
    #pragma unroll
    for (int i = 0; i < 6; ++i) {
        uint32_t lo = min(t, v[i]);
        t = max(t, v[i]);
        v[i] = lo;
    }
}

// Load one 32-code B chunk (4KB) into buf; called by 64 threads of the half
__device__ __forceinline__ void load_bchunk32(uint32_t sb, int code0, int buf, int t64) {
    #pragma unroll
    for (int i = 0; i < 4; ++i) {
        int idx  = t64 + i * 64;             // 0..255
        int code = idx >> 3;                 // 0..31
        int ch   = idx & 7;
        const uint16_t* src = g_ehi + (size_t)(code0 + code) * DD + ch * 8;
        uint32_t doff = SM_B + buf * 4096 + code * 128 + ((ch ^ (code & 7)) * 16);
        CP_ASYNC16(sb + doff, src);
    }
}

__global__ __launch_bounds__(128, 7) void vq_main_mma(
        const float* __restrict__ z,
        const float* __restrict__ emb,
        float* __restrict__ out) {
    __shared__ float swr[4];
    const int tid  = threadIdx.x;
    const int wid  = tid >> 5;
    const int lane = tid & 31;
    const uint32_t sb = smem_u32(smc);

    const int half  = wid >> 1;              // code half this warp screens
    const int mrow0 = (wid & 1) * 32;        // first of this warp's 32 rows
    const int lhalf = tid >> 6;              // cp.async loading half (tid>=64)
    const int t64   = tid & 63;

    const int n0 = blockIdx.x * 64;
    const int b  = n0 >> 11;
    const int t0 = n0 & 2047;
    const float* zb = z + (size_t)b * (DD * TT) + t0;

    // --- Stage A: 2 threads per row, each 32 dims; NEGATED fp16, swizzled
    {
        int r  = tid & 63;
        int hf = tid >> 6;
        const float* zr = zb + r;
        #pragma unroll
        for (int j = 0; j < 16; ++j) {
            int d = hf * 32 + 2 * j;
            __half h0 = __float2half_rn(-zr[(size_t)d * TT]);
            __half h1 = __float2half_rn(-zr[(size_t)(d + 1) * TT]);
            uint32_t hp = (uint32_t)reinterpret_cast<uint16_t&>(h0)
                        | ((uint32_t)reinterpret_cast<uint16_t&>(h1) << 16);
            *(uint32_t*)(smc + SM_AH + SWZ((uint32_t)(r * 128 + 2 * d))) = hp;
        }
    }
    // biased hn table as half2 words
    uint32_t* shn2 = (uint32_t*)(smc + SM_HN);
    #pragma unroll
    for (int i = 0; i < 4; ++i)
        shn2[tid + i * 128] = ((const uint32_t*)g_hnh)[tid + i * 128];

    // Prefetch chunks 0,1 of this thread's loading half
    load_bchunk32(sb, lhalf * 512 + 0 * 32, lhalf * 2 + 0, t64); CP_COMMIT();
    load_bchunk32(sb, lhalf * 512 + 1 * 32, lhalf * 2 + 1, t64); CP_COMMIT();

    __syncthreads();

    // ldmatrix lane constants
    const uint32_t r7 = (uint32_t)(lane & 7);
    const uint32_t mm = (uint32_t)(lane >> 3);

    // --- A fragments: 2 m-tiles/warp (rows mrow0..mrow0+31)
    uint32_t ah[2][4][4];
    #pragma unroll
    for (int mt = 0; mt < 2; ++mt) {
        uint32_t arow = (uint32_t)(mrow0 + mt * 16) + (mm & 1) * 8 + r7;
        uint32_t acol = (mm >> 1) * 16;
        #pragma unroll
        for (int s = 0; s < 4; ++s) {
            uint32_t addr = sb + SM_AH + arow * 128
                          + (((uint32_t)(s * 32) + acol) ^ (r7 * 16));
            LDSM4(ah[mt][s][0], ah[mt][s][1], ah[mt][s][2], ah[mt][s][3], addr);
        }
    }

    const uint32_t blconst = r7 * 128 + ((mm * 16) ^ (r7 * 16));
    const uint32_t q2 = (uint32_t)(half * 512 + (lane & 3) * 2);
    uint32_t ie = q2 | ((q2 + 1) << 16);

    // 4 row-slot trackers: [mt0 row, mt0 row+8, mt1 row, mt1 row+8]
    uint32_t tv[4][2];
    #pragma unroll
    for (int s = 0; s < 4; ++s) { tv[s][0] = 0xFFFFFFFFu; tv[s][1] = 0xFFFFFFFFu; }

    // --- Chunk loop: 16 chunks x 32 codes per half
    #pragma unroll 1
    for (int c = 0; c < 16; ++c) {
        if (c < 15) CP_WAIT1(); else CP_WAIT0();
        __syncthreads();
        const uint32_t bbase = sb + SM_B
                             + (uint32_t)((half * 2 + (c & 1)) * 4096) + blconst;
        const int hnb = half * 256 + c * 16;

        #pragma unroll
        for (int nt = 0; nt < 4; ++nt) {
            uint32_t a1 = bbase + (uint32_t)(nt * 1024);
            uint32_t a2 = a1 ^ 64u;
            uint32_t bh[4][2];
            LDSM4(bh[0][0], bh[0][1], bh[1][0], bh[1][1], a1);
            LDSM4(bh[2][0], bh[2][1], bh[3][0], bh[3][1], a2);

            uint32_t h01 = shn2[hnb + nt * 4 + (lane & 3)];
            uint32_t aA0[2] = {h01, h01};
            uint32_t aA1[2] = {h01, h01};
            MMA_F16A(aA0, ah[0][0], bh[0][0], bh[0][1]);
            MMA_F16A(aA1, ah[1][0], bh[0][0], bh[0][1]);
            MMA_F16A(aA0, ah[0][1], bh[1][0], bh[1][1]);
            MMA_F16A(aA1, ah[1][1], bh[1][0], bh[1][1]);
            MMA_F16A(aA0, ah[0][2], bh[2][0], bh[2][1]);
            MMA_F16A(aA1, ah[1][2], bh[2][0], bh[2][1]);
            MMA_F16A(aA0, ah[0][3], bh[3][0], bh[3][1]);
            MMA_F16A(aA1, ah[1][3], bh[3][0], bh[3][1]);

            uint32_t k0, k1;
            PRMTK(k0, aA0[0], ie, 0x1054);
            PRMTK(k1, aA0[0], ie, 0x3276);
            ins2p(tv[0], k0, k1);
            PRMTK(k0, aA0[1], ie, 0x1054);
            PRMTK(k1, aA0[1], ie, 0x3276);
            ins2p(tv[1], k0, k1);
            PRMTK(k0, aA1[0], ie, 0x1054);
            PRMTK(k1, aA1[0], ie, 0x3276);
            ins2p(tv[2], k0, k1);
            PRMTK(k0, aA1[1], ie, 0x1054);
            PRMTK(k1, aA1[1], ie, 0x3276);
            ins2p(tv[3], k0, k1);
            ie += 0x00080008u;
        }
        __syncthreads();
        if (c < 14) {
            load_bchunk32(sb, lhalf * 512 + (c + 2) * 32,
                          lhalf * 2 + (c & 1), t64);
            CP_COMMIT();
        }
    }

    // --- Quad merge -> per-half top-6 KEYS per row, stored to SMEM
    uint32_t* ky = (uint32_t*)(smc + SM_KEY);   // [half][row][6]
    #pragma unroll
    for (int s = 0; s < 4; ++s) {
        uint32_t m[6] = {tv[s][0], tv[s][1],
                         0xFFFFFFFFu, 0xFFFFFFFFu, 0xFFFFFFFFu, 0xFFFFFFFFu};
        #pragma unroll
        for (int off = 1; off <= 2; off <<= 1) {
            uint32_t p[6];
            #pragma unroll
            for (int j = 0; j < 6; ++j) p[j] = __shfl_xor_sync(0xffffffffu, m[j], off);
            #pragma unroll
            for (int j = 0; j < 6; ++j) ins6u(m, p[j]);
        }
        if ((lane & 3) == 0) {
            int row = mrow0 + (s >> 1) * 16 + (s & 1) * 8 + (lane >> 2);
            #pragma unroll
            for (int j = 0; j < NCAND; ++j)
                ky[(half * 64 + row) * NCAND + j] = m[j];
        }
    }
    __syncthreads();

    // --- Epilogue: 2 threads per row; merge 12 keys -> top-6, exact rescore
    const int row = tid >> 1;
    const int hh  = tid & 1;
    const float* zr = zb + row;

    uint32_t mk[6];
    #pragma unroll
    for (int j = 0; j < 6; ++j) mk[j] = ky[row * NCAND + j];
    #pragma unroll
    for (int j = 0; j < 6; ++j) ins6u(mk, ky[(64 + row) * NCAND + j]);

    float zh[32];
    #pragma unroll
    for (int k = 0; k < 32; ++k) zh[k] = zr[(size_t)(hh * 32 + k) * TT];

    float bestv = 3.4e38f;
    int   besti = 0;
    #pragma unroll
    for (int j = 0; j < NCAND; ++j) {
        int idx = (int)(mk[j] & 0xFFFFu);
        const float4* er = (const float4*)(emb + (size_t)idx * DD + hh * 32);
        float dot = 0.0f;
        #pragma unroll
        for (int q = 0; q < 8; ++q) {
            float4 e4 = __ldg(er + q);
            dot = fmaf(zh[4 * q + 0], e4.x, dot);
            dot = fmaf(zh[4 * q + 1], e4.y, dot);
            dot = fmaf(zh[4 * q + 2], e4.z, dot);
            dot = fmaf(zh[4 * q + 3], e4.w, dot);
        }
        dot += __shfl_xor_sync(0xffffffffu, dot, 1);
        float v = g_hn[idx] - dot;
        if (v < bestv || (v == bestv && idx < besti)) { bestv = v; besti = idx; }
    }

    const float4* er = (const float4*)(emb + (size_t)besti * DD + hh * 32);
    float* oq = out + OFF_Q + (size_t)b * (DD * TT) + t0 + row;
    float* dwp = g_dw + (size_t)besti * DD + hh * 32;
    float lsum = 0.0f;
    #pragma unroll
    for (int q = 0; q < 8; ++q) {
        float4 e4 = __ldg(er + q);
        int d = hh * 32 + 4 * q;
        oq[(size_t)(d + 0) * TT] = e4.x;
        oq[(size_t)(d + 1) * TT] = e4.y;
        oq[(size_t)(d + 2) * TT] = e4.z;
        oq[(size_t)(d + 3) * TT] = e4.w;
        float q0 = e4.x - zh[4 * q + 0], q1 = e4.y - zh[4 * q + 1];
        float q2v = e4.z - zh[4 * q + 2], q3 = e4.w - zh[4 * q + 3];
        lsum += q0 * q0 + q1 * q1 + q2v * q2v + q3 * q3;
        asm volatile("red.global.add.v4.f32 [%0], {%1,%2,%3,%4};"
                     :: "l"(dwp + 4 * q),
                        "f"(zh[4 * q + 0]), "f"(zh[4 * q + 1]),
                        "f"(zh[4 * q + 2]), "f"(zh[4 * q + 3]) : "memory");
    }
    if (hh == 0) {
        out[OFF_CODES + n0 + row] = (float)besti;
        atomicAdd(&g_counts[besti], 1.0f);
    }

    #pragma unroll
    for (int o = 16; o; o >>= 1) lsum += __shfl_xor_sync(0xffffffffu, lsum, o);
    if (lane == 0) swr[wid] = lsum;
    __syncthreads();
    if (tid == 0)
        atomicAdd(&g_loss, swr[0] + swr[1] + swr[2] + swr[3]);
}

// ---------------------------------------------------------------------------
// Finalize (merged): per-block nsum reduction, new_cs/loss (block 0),
// new_w + new_embedding everywhere.  256 blocks x 256 threads.
// ---------------------------------------------------------------------------
__global__ __launch_bounds__(256) void vq_fin(
        const float* __restrict__ ema_cs,
        const float* __restrict__ ema_w,
        float* __restrict__ out) {
    __shared__ float sw[8];
    __shared__ float snv;
    int tid = threadIdx.x;
    int i = blockIdx.x * 256 + tid;

    float s = 0.0f;
    #pragma unroll
    for (int j = 0; j < 4; ++j) {
        int k = tid * 4 + j;
        s += DECAYF * ema_cs[k] + OMD * g_counts[k];
    }
    #pragma unroll
    for (int o = 16; o; o >>= 1) s += __shfl_xor_sync(0xffffffffu, s, o);
    if ((tid & 31) == 0) sw[tid >> 5] = s;
    __syncthreads();
    if (tid < 32) {
        float u = (tid < 8) ? sw[tid] : 0.0f;
        #pragma unroll
        for (int o = 4; o; o >>= 1) u += __shfl_xor_sync(0xffffffffu, u, o);
        if (tid == 0) snv = u;
    }
    __syncthreads();
    float nsum = snv;

    if (blockIdx.x == 0) {
        #pragma unroll
        for (int j = 0; j < 4; ++j) {
            int k = tid * 4 + j;
            out[OFF_NEWCS + k] = DECAYF * ema_cs[k] + OMD * g_counts[k];
        }
        if (tid == 0) out[OFF_LOSS] = COMMITF * g_loss * (1.0f / (float)QE);
    }

    int k = i >> 6;
    float cs = DECAYF * ema_cs[k] + OMD * g_counts[k];
    float cluster = (cs + EPSF) / (nsum + (float)KC * EPSF) * nsum;
    float nw = DECAYF * ema_w[i] + OMD * g_dw[i];
    out[OFF_NEWW + i] = nw;
    out[OFF_NEWEMB + i] = nw * (1.0f / cluster);
}

// ---------------------------------------------------------------------------
extern "C" void kernel_launch(void* const* d_in, const int* in_sizes, int n_in,
                              void* d_out, int out_size) {
    const float* z      = (const float*)d_in[0];
    const float* emb    = (const float*)d_in[1];
    const float* ema_cs = (const float*)d_in[2];
    const float* ema_w  = (const float*)d_in[3];
    float* out = (float*)d_out;

    cudaFuncSetAttribute(vq_main_mma, cudaFuncAttributeMaxDynamicSharedMemorySize, SM_TOTAL);

    vq_prep<<<256, 256>>>(emb);
    vq_main_mma<<<1024, 128, SM_TOTAL>>>(z, emb, out);
    vq_fin<<<256, 256>>>(ema_cs, ema_w, out);
}

// round 16
// speedup vs baseline: 1.3195x; 1.1530x over previous
#include <cuda_runtime.h>
#include <cuda_fp16.h>
#include <cstdint>

// Problem constants
#define KC   1024
#define DD   64
#define BB   32
#define TT   2048
#define NV   (BB*TT)
#define QE   (BB*DD*TT)
#define DECAYF 0.99f
#define OMD    (1.0f - 0.99f)
#define COMMITF 0.25f
#define EPSF 1e-5f
#define NCAND 6
#define NRESC 4
#define HBIAS 64.0f

// Output layout (flat float32, reference tuple order)
#define OFF_Q      0
#define OFF_LOSS   (OFF_Q + QE)
#define OFF_CODES  (OFF_LOSS + 1)
#define OFF_NEWEMB (OFF_CODES + NV)
#define OFF_NEWCS  (OFF_NEWEMB + KC*DD)
#define OFF_NEWW   (OFF_NEWCS + KC)

// Scratch (device globals — no allocation). Zero-initialized at module load;
// g_dw/g_loss are re-zeroed by vq_fin after consumption (cycle invariant).
__device__ float    g_hn[KC];
__device__ uint16_t g_hnh[KC];
__device__ float    g_counts[KC];
__device__ float    g_dw[KC*DD];
__device__ float    g_loss;
__device__ __align__(256) uint16_t g_ehi[KC*DD];

#define SWZ(o) ((o) ^ (((o) >> 3) & 0x70))

__device__ __forceinline__ uint32_t smem_u32(const void* p) {
    uint32_t a;
    asm("{ .reg .u64 t; cvta.to.shared.u64 t, %1; cvt.u32.u64 %0, t; }" : "=r"(a) : "l"(p));
    return a;
}

#define MMA_F16A(acc, A, B0, B1)                                               \
    asm volatile("mma.sync.aligned.m16n8k16.row.col.f16.f16.f16.f16 "          \
        "{%0,%1},{%2,%3,%4,%5},{%6,%7},{%0,%1};"                               \
        : "+r"((acc)[0]), "+r"((acc)[1])                                       \
        : "r"((A)[0]), "r"((A)[1]), "r"((A)[2]), "r"((A)[3]),                  \
          "r"(B0), "r"(B1))

#define LDSM4(r0, r1, r2, r3, a)                                               \
    asm volatile("ldmatrix.sync.aligned.m8n8.x4.shared.b16 {%0,%1,%2,%3}, [%4];" \
        : "=r"(r0), "=r"(r1), "=r"(r2), "=r"(r3) : "r"(a))

#define PRMTK(d, s, i, sel)                                                    \
    asm("prmt.b32 %0, %1, %2, %3;" : "=r"(d) : "r"(s), "r"(i), "n"(sel))

#define CP_ASYNC16(dst_u32, src_ptr)                                           \
    asm volatile("cp.async.cg.shared.global [%0], [%1], 16;"                   \
                 :: "r"(dst_u32), "l"(src_ptr) : "memory")
#define CP_COMMIT() asm volatile("cp.async.commit_group;" ::: "memory")
#define CP_WAIT1()  asm volatile("cp.async.wait_group 1;" ::: "memory")
#define CP_WAIT0()  asm volatile("cp.async.wait_group 0;" ::: "memory")

// SMEM layout: A-fp16 8KB | B 4 buffers x 4KB | hn-half2 2KB
#define SM_AH    0
#define SM_B     8192
#define SM_HN    24576
#define SM_KEY   SM_AH                  // reused after MMA loop (128*6 keys)
#define SM_TOTAL (SM_HN + 2048 + 128)   // 26752

// ---------------------------------------------------------------------------
// Prep: fp16 embedding, warp-per-code half-norms (+bias), counts zero
// ---------------------------------------------------------------------------
__global__ void vq_prep(const float* __restrict__ emb) {
    int i = blockIdx.x * 256 + threadIdx.x;   // 65536 threads
    {
        __half h = __float2half_rn(emb[i]);
        g_ehi[i] = reinterpret_cast<uint16_t&>(h);
    }
    int w = i >> 5;
    int lane = i & 31;
    if (w < KC) {
        const float2* r = (const float2*)(emb + (size_t)w * DD);
        float2 v = r[lane];
        float s = v.x * v.x + v.y * v.y;
        #pragma unroll
        for (int o = 16; o; o >>= 1) s += __shfl_xor_sync(0xffffffffu, s, o);
        if (lane == 0) {
            float hn = 0.5f * s;
            g_hn[w] = hn;
            __half hh = __float2half_rn(hn + HBIAS);
            g_hnh[w] = reinterpret_cast<uint16_t&>(hh);
            g_counts[w] = 0.0f;
        }
    }
}

// ---------------------------------------------------------------------------
// Main: M=64/CTA, warp-pairs split codes; each warp = 2 m-tiles x 512 codes
// ---------------------------------------------------------------------------
extern __shared__ __align__(1024) char smc[];

__device__ __forceinline__ void ins2p(uint32_t v[2], uint32_t a, uint32_t b) {
    uint32_t a0 = min(a, b), a1 = max(a, b);
    uint32_t x = min(v[0], a0);
    uint32_t y = max(v[0], a0);
    uint32_t z = min(v[1], a1);
    v[0] = x;
    v[1] = min(y, z);
}
__device__ __forceinline__ void ins6u(uint32_t v[6], uint32_t t) {
    #pragma unroll
    for (int i = 0; i < 6; ++i) {
        uint32_t lo = min(t, v[i]);
        t = max(t, v[i]);
        v[i] = lo;
    }
}

// Load one 32-code B chunk (4KB) into buf; called by 64 threads of the half
__device__ __forceinline__ void load_bchunk32(uint32_t sb, int code0, int buf, int t64) {
    #pragma unroll
    for (int i = 0; i < 4; ++i) {
        int idx  = t64 + i * 64;             // 0..255
        int code = idx >> 3;                 // 0..31
        int ch   = idx & 7;
        const uint16_t* src = g_ehi + (size_t)(code0 + code) * DD + ch * 8;
        uint32_t doff = SM_B + buf * 4096 + code * 128 + ((ch ^ (code & 7)) * 16);
        CP_ASYNC16(sb + doff, src);
    }
}

__global__ __launch_bounds__(128, 7) void vq_main_mma(
        const float* __restrict__ z,
        const float* __restrict__ emb,
        float* __restrict__ out) {
    __shared__ float swr[4];
    const int tid  = threadIdx.x;
    const int wid  = tid >> 5;
    const int lane = tid & 31;
    const uint32_t sb = smem_u32(smc);

    const int half  = wid >> 1;              // code half this warp screens
    const int mrow0 = (wid & 1) * 32;        // first of this warp's 32 rows
    const int lhalf = tid >> 6;              // cp.async loading half
    const int t64   = tid & 63;

    const int n0 = blockIdx.x * 64;
    const int b  = n0 >> 11;
    const int t0 = n0 & 2047;
    const float* zb = z + (size_t)b * (DD * TT) + t0;

    // --- Stage A: 2 threads per row, each 32 dims; NEGATED fp16, swizzled
    {
        int r  = tid & 63;
        int hf = tid >> 6;
        const float* zr = zb + r;
        #pragma unroll
        for (int j = 0; j < 16; ++j) {
            int d = hf * 32 + 2 * j;
            __half h0 = __float2half_rn(-zr[(size_t)d * TT]);
            __half h1 = __float2half_rn(-zr[(size_t)(d + 1) * TT]);
            uint32_t hp = (uint32_t)reinterpret_cast<uint16_t&>(h0)
                        | ((uint32_t)reinterpret_cast<uint16_t&>(h1) << 16);
            *(uint32_t*)(smc + SM_AH + SWZ((uint32_t)(r * 128 + 2 * d))) = hp;
        }
    }
    // biased hn table as half2 words
    uint32_t* shn2 = (uint32_t*)(smc + SM_HN);
    #pragma unroll
    for (int i = 0; i < 4; ++i)
        shn2[tid + i * 128] = ((const uint32_t*)g_hnh)[tid + i * 128];

    // Prefetch chunks 0,1 of this thread's loading half
    load_bchunk32(sb, lhalf * 512 + 0 * 32, lhalf * 2 + 0, t64); CP_COMMIT();
    load_bchunk32(sb, lhalf * 512 + 1 * 32, lhalf * 2 + 1, t64); CP_COMMIT();

    __syncthreads();

    // ldmatrix lane constants
    const uint32_t r7 = (uint32_t)(lane & 7);
    const uint32_t mm = (uint32_t)(lane >> 3);

    // --- A fragments: 2 m-tiles/warp (rows mrow0..mrow0+31)
    uint32_t ah[2][4][4];
    #pragma unroll
    for (int mt = 0; mt < 2; ++mt) {
        uint32_t arow = (uint32_t)(mrow0 + mt * 16) + (mm & 1) * 8 + r7;
        uint32_t acol = (mm >> 1) * 16;
        #pragma unroll
        for (int s = 0; s < 4; ++s) {
            uint32_t addr = sb + SM_AH + arow * 128
                          + (((uint32_t)(s * 32) + acol) ^ (r7 * 16));
            LDSM4(ah[mt][s][0], ah[mt][s][1], ah[mt][s][2], ah[mt][s][3], addr);
        }
    }

    const uint32_t blconst = r7 * 128 + ((mm * 16) ^ (r7 * 16));
    const uint32_t q2 = (uint32_t)(half * 512 + (lane & 3) * 2);
    uint32_t ie = q2 | ((q2 + 1) << 16);

    // 4 row-slot trackers: [mt0 row, mt0 row+8, mt1 row, mt1 row+8]
    uint32_t tv[4][2];
    #pragma unroll
    for (int s = 0; s < 4; ++s) { tv[s][0] = 0xFFFFFFFFu; tv[s][1] = 0xFFFFFFFFu; }

    // --- Chunk loop: 16 chunks x 32 codes per half
    #pragma unroll 1
    for (int c = 0; c < 16; ++c) {
        if (c < 15) CP_WAIT1(); else CP_WAIT0();
        __syncthreads();
        const uint32_t bbase = sb + SM_B
                             + (uint32_t)((half * 2 + (c & 1)) * 4096) + blconst;
        const int hnb = half * 256 + c * 16;

        #pragma unroll
        for (int nt = 0; nt < 4; ++nt) {
            uint32_t a1 = bbase + (uint32_t)(nt * 1024);
            uint32_t a2 = a1 ^ 64u;
            uint32_t bh[4][2];
            LDSM4(bh[0][0], bh[0][1], bh[1][0], bh[1][1], a1);
            LDSM4(bh[2][0], bh[2][1], bh[3][0], bh[3][1], a2);

            uint32_t h01 = shn2[hnb + nt * 4 + (lane & 3)];
            uint32_t aA0[2] = {h01, h01};
            uint32_t aA1[2] = {h01, h01};
            MMA_F16A(aA0, ah[0][0], bh[0][0], bh[0][1]);
            MMA_F16A(aA1, ah[1][0], bh[0][0], bh[0][1]);
            MMA_F16A(aA0, ah[0][1], bh[1][0], bh[1][1]);
            MMA_F16A(aA1, ah[1][1], bh[1][0], bh[1][1]);
            MMA_F16A(aA0, ah[0][2], bh[2][0], bh[2][1]);
            MMA_F16A(aA1, ah[1][2], bh[2][0], bh[2][1]);
            MMA_F16A(aA0, ah[0][3], bh[3][0], bh[3][1]);
            MMA_F16A(aA1, ah[1][3], bh[3][0], bh[3][1]);

            uint32_t k0, k1;
            PRMTK(k0, aA0[0], ie, 0x1054);
            PRMTK(k1, aA0[0], ie, 0x3276);
            ins2p(tv[0], k0, k1);
            PRMTK(k0, aA0[1], ie, 0x1054);
            PRMTK(k1, aA0[1], ie, 0x3276);
            ins2p(tv[1], k0, k1);
            PRMTK(k0, aA1[0], ie, 0x1054);
            PRMTK(k1, aA1[0], ie, 0x3276);
            ins2p(tv[2], k0, k1);
            PRMTK(k0, aA1[1], ie, 0x1054);
            PRMTK(k1, aA1[1], ie, 0x3276);
            ins2p(tv[3], k0, k1);
            ie += 0x00080008u;
        }
        __syncthreads();
        if (c < 14) {
            load_bchunk32(sb, lhalf * 512 + (c + 2) * 32,
                          lhalf * 2 + (c & 1), t64);
            CP_COMMIT();
        }
    }

    // --- Quad merge -> per-half top-6 KEYS per row, stored to SMEM
    uint32_t* ky = (uint32_t*)(smc + SM_KEY);   // [half][row][6]
    #pragma unroll
    for (int s = 0; s < 4; ++s) {
        uint32_t m[6] = {tv[s][0], tv[s][1],
                         0xFFFFFFFFu, 0xFFFFFFFFu, 0xFFFFFFFFu, 0xFFFFFFFFu};
        #pragma unroll
        for (int off = 1; off <= 2; off <<= 1) {
            uint32_t p[6];
            #pragma unroll
            for (int j = 0; j < 6; ++j) p[j] = __shfl_xor_sync(0xffffffffu, m[j], off);
            #pragma unroll
            for (int j = 0; j < 6; ++j) ins6u(m, p[j]);
        }
        if ((lane & 3) == 0) {
            int row = mrow0 + (s >> 1) * 16 + (s & 1) * 8 + (lane >> 2);
            #pragma unroll
            for (int j = 0; j < NCAND; ++j)
                ky[(half * 64 + row) * NCAND + j] = m[j];
        }
    }
    __syncthreads();

    // --- Epilogue: 2 threads per row; merge 12 keys -> rescore top-4 exactly
    const int row = tid >> 1;
    const int hh  = tid & 1;
    const float* zr = zb + row;

    uint32_t mk[6];
    #pragma unroll
    for (int j = 0; j < 6; ++j) mk[j] = ky[row * NCAND + j];
    #pragma unroll
    for (int j = 0; j < 6; ++j) ins6u(mk, ky[(64 + row) * NCAND + j]);

    float zh[32];
    #pragma unroll
    for (int k = 0; k < 32; ++k) zh[k] = zr[(size_t)(hh * 32 + k) * TT];

    float bestv = 3.4e38f;
    int   besti = 0;
    #pragma unroll
    for (int j = 0; j < NRESC; ++j) {
        int idx = (int)(mk[j] & 0xFFFFu);
        const float4* er = (const float4*)(emb + (size_t)idx * DD + hh * 32);
        float dot = 0.0f;
        #pragma unroll
        for (int q = 0; q < 8; ++q) {
            float4 e4 = __ldg(er + q);
            dot = fmaf(zh[4 * q + 0], e4.x, dot);
            dot = fmaf(zh[4 * q + 1], e4.y, dot);
            dot = fmaf(zh[4 * q + 2], e4.z, dot);
            dot = fmaf(zh[4 * q + 3], e4.w, dot);
        }
        dot += __shfl_xor_sync(0xffffffffu, dot, 1);
        float v = g_hn[idx] - dot;
        if (v < bestv || (v == bestv && idx < besti)) { bestv = v; besti = idx; }
    }

    const float4* er = (const float4*)(emb + (size_t)besti * DD + hh * 32);
    float* oq = out + OFF_Q + (size_t)b * (DD * TT) + t0 + row;
    float* dwp = g_dw + (size_t)besti * DD + hh * 32;
    float lsum = 0.0f;
    #pragma unroll
    for (int q = 0; q < 8; ++q) {
        float4 e4 = __ldg(er + q);
        int d = hh * 32 + 4 * q;
        oq[(size_t)(d + 0) * TT] = e4.x;
        oq[(size_t)(d + 1) * TT] = e4.y;
        oq[(size_t)(d + 2) * TT] = e4.z;
        oq[(size_t)(d + 3) * TT] = e4.w;
        float q0 = e4.x - zh[4 * q + 0], q1 = e4.y - zh[4 * q + 1];
        float q2v = e4.z - zh[4 * q + 2], q3 = e4.w - zh[4 * q + 3];
        lsum += q0 * q0 + q1 * q1 + q2v * q2v + q3 * q3;
        asm volatile("red.global.add.v4.f32 [%0], {%1,%2,%3,%4};"
                     :: "l"(dwp + 4 * q),
                        "f"(zh[4 * q + 0]), "f"(zh[4 * q + 1]),
                        "f"(zh[4 * q + 2]), "f"(zh[4 * q + 3]) : "memory");
    }
    if (hh == 0) {
        out[OFF_CODES + n0 + row] = (float)besti;
        atomicAdd(&g_counts[besti], 1.0f);
    }

    #pragma unroll
    for (int o = 16; o; o >>= 1) lsum += __shfl_xor_sync(0xffffffffu, lsum, o);
    if (lane == 0) swr[wid] = lsum;
    __syncthreads();
    if (tid == 0)
        atomicAdd(&g_loss, swr[0] + swr[1] + swr[2] + swr[3]);
}

// ---------------------------------------------------------------------------
// Finalize (merged): per-block nsum reduction, new_cs/loss (block 0),
// new_w + new_embedding everywhere; re-zeroes g_dw / g_loss after reading.
// ---------------------------------------------------------------------------
__global__ __launch_bounds__(256) void vq_fin(
        const float* __restrict__ ema_cs,
        const float* __restrict__ ema_w,
        float* __restrict__ out) {
    __shared__ float sw[8];
    __shared__ float snv;
    int tid = threadIdx.x;
    int i = blockIdx.x * 256 + tid;

    float s = 0.0f;
    #pragma unroll
    for (int j = 0; j < 4; ++j) {
        int k = tid * 4 + j;
        s += DECAYF * ema_cs[k] + OMD * g_counts[k];
    }
    #pragma unroll
    for (int o = 16; o; o >>= 1) s += __shfl_xor_sync(0xffffffffu, s, o);
    if ((tid & 31) == 0) sw[tid >> 5] = s;
    __syncthreads();
    if (tid < 32) {
        float u = (tid < 8) ? sw[tid] : 0.0f;
        #pragma unroll
        for (int o = 4; o; o >>= 1) u += __shfl_xor_sync(0xffffffffu, u, o);
        if (tid == 0) snv = u;
    }
    __syncthreads();
    float nsum = snv;

    if (blockIdx.x == 0) {
        #pragma unroll
        for (int j = 0; j < 4; ++j) {
            int k = tid * 4 + j;
            out[OFF_NEWCS + k] = DECAYF * ema_cs[k] + OMD * g_counts[k];
        }
        if (tid == 0) {
            out[OFF_LOSS] = COMMITF * g_loss * (1.0f / (float)QE);
            g_loss = 0.0f;                 // reset scratch for next replay
        }
    }

    int k = i >> 6;
    float cs = DECAYF * ema_cs[k] + OMD * g_counts[k];
    float cluster = (cs + EPSF) / (nsum + (float)KC * EPSF) * nsum;
    float dwv = g_dw[i];
    g_dw[i] = 0.0f;                        // reset scratch for next replay
    float nw = DECAYF * ema_w[i] + OMD * dwv;
    out[OFF_NEWW + i] = nw;
    out[OFF_NEWEMB + i] = nw * (1.0f / cluster);
}

// ---------------------------------------------------------------------------
extern "C" void kernel_launch(void* const* d_in, const int* in_sizes, int n_in,
                              void* d_out, int out_size) {
    const float* z      = (const float*)d_in[0];
    const float* emb    = (const float*)d_in[1];
    const float* ema_cs = (const float*)d_in[2];
    const float* ema_w  = (const float*)d_in[3];
    float* out = (float*)d_out;

    cudaFuncSetAttribute(vq_main_mma, cudaFuncAttributeMaxDynamicSharedMemorySize, SM_TOTAL);

    vq_prep<<<256, 256>>>(emb);
    vq_main_mma<<<1024, 128, SM_TOTAL>>>(z, emb, out);
    vq_fin<<<256, 256>>>(ema_cs, ema_w, out);
}